// round 3
// baseline (speedup 1.0000x reference)
#include <cuda_runtime.h>

// BackProjection: B=2, A=180, HR=512, H=W=512, pad=51, Hp=Wp=614
#define A_N   180
#define HR_N  512
#define HOUT  512
#define HP    614
#define WPF   614.0f

// Per-angle column profile, both batches interleaved: g_col[a*HP + y] = (b0, b1)
__device__ float2 g_col[A_N * HP];

__global__ void col_kernel(const float* __restrict__ sino) {
    int idx = blockIdx.x * blockDim.x + threadIdx.x;
    if (idx >= A_N * HP) return;
    int a = idx / HP;
    int y = idx - a * HP;
    float src = ((float)y + 0.5f) * ((float)HR_N / (float)HP) - 0.5f;
    src = fminf(fmaxf(src, 0.0f), (float)(HR_N - 1));
    int i0 = (int)floorf(src);
    int i1 = min(i0 + 1, HR_N - 1);
    float w = src - (float)i0;
    const float* s0 = sino + a * HR_N;                 // b = 0
    const float* s1 = sino + A_N * HR_N + a * HR_N;    // b = 1
    float v0 = s0[i0] * (1.0f - w) + s0[i1] * w;
    float v1 = s1[i0] * (1.0f - w) + s1[i1] * w;
    g_col[idx] = make_float2(v0, v1);
}

__global__ __launch_bounds__(256) void bp_kernel(const float* __restrict__ angles,
                                                 float* __restrict__ out) {
    __shared__ float2 sh_cs[A_N];   // (cos, sin) of th = -deg2rad(angle)
    int t = threadIdx.y * 32 + threadIdx.x;
    if (t < A_N) {
        float th = -angles[t] * 0.017453292519943295f;
        sh_cs[t] = make_float2(cosf(th), sinf(th));
    }
    __syncthreads();

    int x = blockIdx.x * 32 + threadIdx.x;
    int y = blockIdx.y * 8 + threadIdx.y;
    // padded coords (x+51), center 306.5:  X = (x+51) - 306.5 = x - 255.5
    float Xp = (float)x - 255.5f;
    float Yp = (float)y - 255.5f;

    float accx = 0.0f, accy = 0.0f;
    const float2* colA = g_col;

    #pragma unroll 4
    for (int a = 0; a < A_N; ++a, colA += HP) {
        float2 cs = sh_cs[a];
        float c = cs.x, s = cs.y;
        float ix = fmaf(c, Xp, fmaf(-s, Yp, 306.5f));
        float iy = fmaf(s, Xp, fmaf(c, Yp, 306.5f));

        // Fast path: all 4 corners valid, no clamping, wxe == 1
        bool fast = (ix >= 0.0f) & (ix < 613.0f) & (iy >= 0.0f) & (iy < 613.0f);
        if (__all_sync(0xffffffffu, fast)) {
            int y0 = (int)iy;                 // iy >= 0 -> trunc == floor
            float wy = iy - (float)y0;
            float2 c0 = colA[y0];
            float2 c1 = colA[y0 + 1];
            float w0 = 1.0f - wy;
            accx = fmaf(w0, c0.x, accx); accx = fmaf(wy, c1.x, accx);
            accy = fmaf(w0, c0.y, accy); accy = fmaf(wy, c1.y, accy);
        } else {
            // General path (matches reference masking/clamping exactly)
            float x0f = floorf(ix);
            float wx = ix - x0f;
            float wxe = 0.0f;
            if ((ix >= 0.0f) & (ix < 614.0f))  wxe  = 1.0f - wx;   // vx0
            if ((ix >= -1.0f) & (ix < 613.0f)) wxe += wx;          // vx1
            float y0f = floorf(iy);
            float wy = iy - y0f;
            int y0 = (int)y0f;
            float wy0 = ((iy >= 0.0f) & (iy < 614.0f))  ? (1.0f - wy) * wxe : 0.0f;
            float wy1 = ((iy >= -1.0f) & (iy < 613.0f)) ? wy * wxe : 0.0f;
            int y0c = min(max(y0, 0), HP - 1);
            int y1c = min(max(y0 + 1, 0), HP - 1);
            float2 c0 = colA[y0c];
            float2 c1 = colA[y1c];
            accx = fmaf(wy0, c0.x, accx); accx = fmaf(wy1, c1.x, accx);
            accy = fmaf(wy0, c0.y, accy); accy = fmaf(wy1, c1.y, accy);
        }
    }

    const float scale = (float)(1.0 / (180.0 + 1e-6));
    int o = y * HOUT + x;
    out[o] = accx * scale;
    out[o + HOUT * HOUT] = accy * scale;   // batch 1 (out shape (2,1,512,512))
}

extern "C" void kernel_launch(void* const* d_in, const int* in_sizes, int n_in,
                              void* d_out, int out_size) {
    const float* sino   = (const float*)d_in[0];
    const float* angles = (const float*)d_in[1];
    float* out = (float*)d_out;

    col_kernel<<<(A_N * HP + 255) / 256, 256>>>(sino);

    dim3 blk(32, 8);
    dim3 grd(HOUT / 32, HOUT / 8);   // 16 x 64 = 1024 CTAs, ~1 wave at 7 CTA/SM
    bp_kernel<<<grd, blk>>>(angles, out);
}

// round 6
// speedup vs baseline: 1.1034x; 1.1034x over previous
#include <cuda_runtime.h>

// BackProjection: B=2, A=180, HR=512, H=W=512, pad=51, Hp=Wp=614
#define A_N   180
#define HR_N  512
#define HOUT  512
#define HP    614

// Per-angle column profiles.
// g_col [a*HP + y] = (b0[y], b1[y])                          (general path)
// g_col4[a*HP + y] = (b0[y], b1[y], b0[y+1c], b1[y+1c])      (fast path, 1x LDG.128)
__device__ float2 g_col [A_N * HP];
__device__ float4 g_col4[A_N * HP];

__device__ __forceinline__ float2 col_at(const float* __restrict__ sino, int a, int y) {
    float src = ((float)y + 0.5f) * ((float)HR_N / (float)HP) - 0.5f;
    src = fminf(fmaxf(src, 0.0f), (float)(HR_N - 1));
    int i0 = (int)src;                       // src >= 0
    int i1 = min(i0 + 1, HR_N - 1);
    float w = src - (float)i0;
    const float* s0 = sino + a * HR_N;                 // b = 0
    const float* s1 = sino + A_N * HR_N + a * HR_N;    // b = 1
    // match reference rounding: p0*(1-w) + p1*w
    float v0 = s0[i0] * (1.0f - w) + s0[i1] * w;
    float v1 = s1[i0] * (1.0f - w) + s1[i1] * w;
    return make_float2(v0, v1);
}

__global__ void col_kernel(const float* __restrict__ sino) {
    int idx = blockIdx.x * blockDim.x + threadIdx.x;
    if (idx >= A_N * HP) return;
    int a = idx / HP;
    int y = idx - a * HP;
    float2 c0 = col_at(sino, a, y);
    float2 c1 = col_at(sino, a, min(y + 1, HP - 1));
    g_col[idx]  = c0;
    g_col4[idx] = make_float4(c0.x, c0.y, c1.x, c1.y);
}

__global__ __launch_bounds__(256) void bp_kernel(const float* __restrict__ angles,
                                                 float* __restrict__ out) {
    __shared__ float2 sh_cs[A_N];   // (cos, sin) of th = -deg2rad(angle)
    int t = threadIdx.y * 32 + threadIdx.x;
    if (t < A_N) {
        float th = -angles[t] * 0.017453292519943295f;
        sh_cs[t] = make_float2(cosf(th), sinf(th));
    }
    __syncthreads();

    int x = blockIdx.x * 32 + threadIdx.x;
    int y = blockIdx.y * 8 + threadIdx.y;
    // padded coords (x+51), center 306.5:  X = (x+51) - 306.5 = x - 255.5
    float Xp = (float)x - 255.5f;
    float Yp = (float)y - 255.5f;

    float a0x = 0.0f, a0y = 0.0f, a1x = 0.0f, a1y = 0.0f;

    // Interior test: for all angles |c*Xp - s*Yp| <= r and |s*Xp + c*Yp| <= r,
    // with r = sqrt(Xp^2 + Yp^2). r^2 < 93500 (r < ~305.8) => ix, iy strictly
    // inside (0.5, 612.5) for every angle: no clamping, wxe == 1,
    // y0 in [0, 612], y0+1 <= 613 (covered by g_col4).
    bool interior = fmaf(Xp, Xp, Yp * Yp) < 93500.0f;

    if (interior) {
        const float4* __restrict__ colA = g_col4;
        #pragma unroll 4
        for (int a = 0; a < A_N; a += 2, colA += 2 * HP) {
            {
                float2 cs = sh_cs[a];
                float iy = fmaf(cs.y, Xp, fmaf(cs.x, Yp, 306.5f));
                int   y0 = (int)iy;                 // iy > 0 -> trunc == floor
                float wy = iy - (float)y0;
                float4 cc = colA[y0];
                float w0 = 1.0f - wy;
                a0x = fmaf(w0, cc.x, a0x);
                a0y = fmaf(w0, cc.y, a0y);
                a0x = fmaf(wy, cc.z, a0x);
                a0y = fmaf(wy, cc.w, a0y);
            }
            {
                float2 cs = sh_cs[a + 1];
                float iy = fmaf(cs.y, Xp, fmaf(cs.x, Yp, 306.5f));
                int   y0 = (int)iy;
                float wy = iy - (float)y0;
                float4 cc = colA[HP + y0];
                float w0 = 1.0f - wy;
                a1x = fmaf(w0, cc.x, a1x);
                a1y = fmaf(w0, cc.y, a1y);
                a1x = fmaf(wy, cc.z, a1x);
                a1y = fmaf(wy, cc.w, a1y);
            }
        }
    } else {
        // General path (matches reference masking/clamping exactly)
        const float2* __restrict__ colA = g_col;
        #pragma unroll 2
        for (int a = 0; a < A_N; ++a, colA += HP) {
            float2 cs = sh_cs[a];
            float c = cs.x, s = cs.y;
            float ix = fmaf(c, Xp, fmaf(-s, Yp, 306.5f));
            float iy = fmaf(s, Xp, fmaf(c, Yp, 306.5f));
            float x0f = floorf(ix);
            float wx = ix - x0f;
            float wxe = 0.0f;
            if ((ix >= 0.0f) & (ix < 614.0f))  wxe  = 1.0f - wx;   // vx0
            if ((ix >= -1.0f) & (ix < 613.0f)) wxe += wx;          // vx1
            float y0f = floorf(iy);
            float wy = iy - y0f;
            int y0 = (int)y0f;
            float wy0 = ((iy >= 0.0f) & (iy < 614.0f))  ? (1.0f - wy) * wxe : 0.0f;
            float wy1 = ((iy >= -1.0f) & (iy < 613.0f)) ? wy * wxe : 0.0f;
            int y0c = min(max(y0, 0), HP - 1);
            int y1c = min(max(y0 + 1, 0), HP - 1);
            float2 c0 = colA[y0c];
            float2 c1 = colA[y1c];
            a0x = fmaf(wy0, c0.x, a0x);
            a0y = fmaf(wy0, c0.y, a0y);
            a0x = fmaf(wy1, c1.x, a0x);
            a0y = fmaf(wy1, c1.y, a0y);
        }
    }

    const float scale = (float)(1.0 / (180.0 + 1e-6));
    int o = y * HOUT + x;
    out[o]               = (a0x + a1x) * scale;
    out[o + HOUT * HOUT] = (a0y + a1y) * scale;   // batch 1 (out shape (2,1,512,512))
}

extern "C" void kernel_launch(void* const* d_in, const int* in_sizes, int n_in,
                              void* d_out, int out_size) {
    const float* sino   = (const float*)d_in[0];
    const float* angles = (const float*)d_in[1];
    float* out = (float*)d_out;

    col_kernel<<<(A_N * HP + 255) / 256, 256>>>(sino);

    dim3 blk(32, 8);
    dim3 grd(HOUT / 32, HOUT / 8);   // 16 x 64 = 1024 CTAs
    bp_kernel<<<grd, blk>>>(angles, out);
}

// round 7
// speedup vs baseline: 1.7475x; 1.5838x over previous
#include <cuda_runtime.h>

// BackProjection: B=2, A=180, HR=512, H=W=512, pad=51, Hp=Wp=614
#define A_N   180
#define HR_N  512
#define HOUT  512
#define HP    614
#define PADR  64            // zero-pad rows each side (covers y0 in [-56, 667])
#define HPP   (HP + 2*PADR) // 742 rows per angle

// Zero-padded per-angle column profile, both batches + next row fused:
// row y (logical, y in [-PADR, HP+PADR)) holds (b0[y], b1[y], b0[y+1], b1[y+1])
// where b*[y] == 0 outside [0, HP-1]. One LDG.128 gives a full bilinear-y pair.
__device__ float4 g_col4p[A_N * HPP];

__device__ __forceinline__ float2 col_at(const float* __restrict__ sino, int a, int y) {
    float src = ((float)y + 0.5f) * ((float)HR_N / (float)HP) - 0.5f;
    src = fminf(fmaxf(src, 0.0f), (float)(HR_N - 1));
    int i0 = (int)src;                       // src >= 0
    int i1 = min(i0 + 1, HR_N - 1);
    float w = src - (float)i0;
    const float* s0 = sino + a * HR_N;                 // b = 0
    const float* s1 = sino + A_N * HR_N + a * HR_N;    // b = 1
    // match reference rounding: p0*(1-w) + p1*w
    float v0 = s0[i0] * (1.0f - w) + s0[i1] * w;
    float v1 = s1[i0] * (1.0f - w) + s1[i1] * w;
    return make_float2(v0, v1);
}

__global__ void col_kernel(const float* __restrict__ sino) {
    int idx = blockIdx.x * blockDim.x + threadIdx.x;
    if (idx >= A_N * HPP) return;
    int a  = idx / HPP;
    int y  = idx - a * HPP - PADR;          // logical row
    float2 c0 = (y     >= 0 && y     < HP) ? col_at(sino, a, y)     : make_float2(0.f, 0.f);
    float2 c1 = (y + 1 >= 0 && y + 1 < HP) ? col_at(sino, a, y + 1) : make_float2(0.f, 0.f);
    g_col4p[idx] = make_float4(c0.x, c0.y, c1.x, c1.y);
}

__global__ __launch_bounds__(256) void bp_kernel(const float* __restrict__ angles,
                                                 float* __restrict__ out) {
    __shared__ float2 sh_cs[A_N];   // (cos, sin) of th = -deg2rad(angle)
    int t = threadIdx.y * 32 + threadIdx.x;
    if (t < A_N) {
        float th = -angles[t] * 0.017453292519943295f;
        sh_cs[t] = make_float2(cosf(th), sinf(th));
    }
    __syncthreads();

    int x = blockIdx.x * 32 + threadIdx.x;
    int y = blockIdx.y * 8 + threadIdx.y;
    // padded coords (x+51), center 306.5:  X = (x+51) - 306.5 = x - 255.5
    float Xp = (float)x - 255.5f;
    float Yp = (float)y - 255.5f;

    float a0x = 0.0f, a0y = 0.0f, a1x = 0.0f, a1y = 0.0f;

    // Interior: r^2 < 93500 (r < 305.8) => ix, iy in (0.5, 612.5) for all angles:
    // all 4 corners valid, wxe == 1, y0 in [0,612]. Warp-uniform branch so a
    // straddling warp executes exactly ONE of the two loops.
    bool interior = fmaf(Xp, Xp, Yp * Yp) < 93500.0f;

    if (__all_sync(0xffffffffu, interior)) {
        const float4* __restrict__ colA = g_col4p + PADR;
        #pragma unroll 4
        for (int a = 0; a < A_N; a += 2, colA += 2 * HPP) {
            {
                float2 cs = sh_cs[a];
                float iy = fmaf(cs.y, Xp, fmaf(cs.x, Yp, 306.5f));
                int   y0 = (int)iy;                 // iy > 0 -> trunc == floor
                float wy = iy - (float)y0;
                float4 cc = colA[y0];
                float w0 = 1.0f - wy;
                a0x = fmaf(w0, cc.x, a0x);
                a0y = fmaf(w0, cc.y, a0y);
                a0x = fmaf(wy, cc.z, a0x);
                a0y = fmaf(wy, cc.w, a0y);
            }
            {
                float2 cs = sh_cs[a + 1];
                float iy = fmaf(cs.y, Xp, fmaf(cs.x, Yp, 306.5f));
                int   y0 = (int)iy;
                float wy = iy - (float)y0;
                float4 cc = colA[HPP + y0];
                float w0 = 1.0f - wy;
                a1x = fmaf(w0, cc.x, a1x);
                a1y = fmaf(w0, cc.y, a1y);
                a1x = fmaf(wy, cc.z, a1x);
                a1y = fmaf(wy, cc.w, a1y);
            }
        }
    } else {
        // General path. Zero-padded table removes all y masking/clamping;
        // x masking collapses to wxe = clamp(min(ix+1, 614-ix), 0, 1):
        //   ix in [-1,0):  vx0=0, vx1=1 -> wxe = wx   = ix+1
        //   ix in [0,613): vx0=vx1=1    -> wxe = 1
        //   ix in [613,614): vx0=1,vx1=0-> wxe = 1-wx = 614-ix
        //   else 0.
        const float4* __restrict__ colA = g_col4p + PADR;
        #pragma unroll 2
        for (int a = 0; a < A_N; ++a, colA += HPP) {
            float2 cs = sh_cs[a];
            float c = cs.x, s = cs.y;
            float ix = fmaf(c, Xp, fmaf(-s, Yp, 306.5f));
            float iy = fmaf(s, Xp, fmaf(c, Yp, 306.5f));
            float wxe = fmaxf(fminf(fminf(ix + 1.0f, 614.0f - ix), 1.0f), 0.0f);
            float y0f = floorf(iy);
            int   y0  = (int)y0f;               // in [-56, 667] -> padded range
            float wy  = iy - y0f;
            float4 cc = colA[y0];
            float w0 = (1.0f - wy) * wxe;
            float w1 = wy * wxe;
            a0x = fmaf(w0, cc.x, a0x);
            a0y = fmaf(w0, cc.y, a0y);
            a0x = fmaf(w1, cc.z, a0x);
            a0y = fmaf(w1, cc.w, a0y);
        }
    }

    const float scale = (float)(1.0 / (180.0 + 1e-6));
    int o = y * HOUT + x;
    out[o]               = (a0x + a1x) * scale;
    out[o + HOUT * HOUT] = (a0y + a1y) * scale;   // batch 1 (out shape (2,1,512,512))
}

extern "C" void kernel_launch(void* const* d_in, const int* in_sizes, int n_in,
                              void* d_out, int out_size) {
    const float* sino   = (const float*)d_in[0];
    const float* angles = (const float*)d_in[1];
    float* out = (float*)d_out;

    col_kernel<<<(A_N * HPP + 255) / 256, 256>>>(sino);

    dim3 blk(32, 8);
    dim3 grd(HOUT / 32, HOUT / 8);   // 16 x 64 = 1024 CTAs, single resident wave
    bp_kernel<<<grd, blk>>>(angles, out);
}